// round 5
// baseline (speedup 1.0000x reference)
#include <cuda_runtime.h>
#include <cuda_bf16.h>
#include <math.h>
#include <stdint.h>

#define Bb 8
#define Tt 1024
#define Cc 1024
#define NHEAD 16
#define HDIM 64
#define BHt (Bb*NHEAD)     // 128
#define Mm (Bb*Tt)         // 8192
#define N1 (3*Cc)          // 3072
#define KT 32              // 1024/32 k-tiles

// ------------------------- device scratch (no allocs allowed) --------------
__device__ __nv_bfloat16 g_xhi[(size_t)Mm*Cc],  g_xlo[(size_t)Mm*Cc];
__device__ __nv_bfloat16 g_w1hi[(size_t)N1*Cc], g_w1lo[(size_t)N1*Cc];
__device__ __nv_bfloat16 g_w2hi[(size_t)Cc*Cc], g_w2lo[(size_t)Cc*Cc];
__device__ __nv_bfloat16 g_yhi[(size_t)Mm*Cc],  g_ylo[(size_t)Mm*Cc];
__device__ float g_Q [(size_t)BHt*Tt*HDIM];   // fp32 pre-rope [bh][t][d]
__device__ float g_K [(size_t)BHt*Tt*HDIM];
__device__ __nv_bfloat16 g_Qhi[(size_t)BHt*Tt*HDIM], g_Qlo[(size_t)BHt*Tt*HDIM]; // post-rope, x0.125
__device__ __nv_bfloat16 g_Khi[(size_t)BHt*Tt*HDIM], g_Klo[(size_t)BHt*Tt*HDIM];
__device__ __nv_bfloat16 g_Vthi[(size_t)BHt*HDIM*Tt], g_Vtlo[(size_t)BHt*HDIM*Tt]; // [bh][d][t]

// ------------------------------ PTX helpers --------------------------------
__device__ __forceinline__ uint32_t smem_u32(const void* p) {
    uint32_t a;
    asm("{ .reg .u64 t; cvta.to.shared.u64 t, %1; cvt.u32.u64 %0, t; }"
        : "=r"(a) : "l"(p));
    return a;
}

#define CP16(dst, src) \
    asm volatile("cp.async.cg.shared.global [%0], [%1], 16;" \
                 :: "r"(dst), "l"(src) : "memory")
#define CP_COMMIT() asm volatile("cp.async.commit_group;" ::: "memory")
#define CP_WAIT1()  asm volatile("cp.async.wait_group 1;" ::: "memory")
#define CP_WAIT0()  asm volatile("cp.async.wait_group 0;" ::: "memory")

#define LDSM4(r0, r1, r2, r3, a) \
    asm volatile("ldmatrix.sync.aligned.m8n8.x4.shared.b16 {%0,%1,%2,%3}, [%4];" \
                 : "=r"(r0), "=r"(r1), "=r"(r2), "=r"(r3) : "r"(a))

__device__ __forceinline__ void mma16816(float c[4], const uint32_t a[4],
                                         uint32_t b0, uint32_t b1) {
    asm volatile("mma.sync.aligned.m16n8k16.row.col.f32.bf16.bf16.f32 "
                 "{%0,%1,%2,%3}, {%4,%5,%6,%7}, {%8,%9}, {%0,%1,%2,%3};"
                 : "+f"(c[0]), "+f"(c[1]), "+f"(c[2]), "+f"(c[3])
                 : "r"(a[0]), "r"(a[1]), "r"(a[2]), "r"(a[3]),
                   "r"(b0), "r"(b1));
}

// two floats -> packed bf16x2 hi + residual lo
__device__ __forceinline__ void split2(float x, float y, uint32_t& hi, uint32_t& lo) {
    __nv_bfloat162 h = __floats2bfloat162_rn(x, y);
    float2 hf = __bfloat1622float2(h);
    __nv_bfloat162 l = __floats2bfloat162_rn(x - hf.x, y - hf.y);
    hi = *reinterpret_cast<uint32_t*>(&h);
    lo = *reinterpret_cast<uint32_t*>(&l);
}

// ---------------------------------------------------------------------------
// fp32 -> bf16 hi/lo split conversion
// ---------------------------------------------------------------------------
template<int W>
__global__ __launch_bounds__(256)
void cvt_kernel(const float* __restrict__ src, int n4)
{
    int i = blockIdx.x * blockDim.x + threadIdx.x;
    if (i >= n4) return;
    __nv_bfloat16* hi = (W == 0) ? g_xhi : (W == 1) ? g_w1hi : g_w2hi;
    __nv_bfloat16* lo = (W == 0) ? g_xlo : (W == 1) ? g_w1lo : g_w2lo;
    float4 v = ((const float4*)src)[i];
    __nv_bfloat162 h01 = __floats2bfloat162_rn(v.x, v.y);
    __nv_bfloat162 h23 = __floats2bfloat162_rn(v.z, v.w);
    float2 f01 = __bfloat1622float2(h01);
    float2 f23 = __bfloat1622float2(h23);
    __nv_bfloat162 l01 = __floats2bfloat162_rn(v.x - f01.x, v.y - f01.y);
    __nv_bfloat162 l23 = __floats2bfloat162_rn(v.z - f23.x, v.w - f23.y);
    ((__nv_bfloat162*)hi)[i*2]     = h01;
    ((__nv_bfloat162*)hi)[i*2 + 1] = h23;
    ((__nv_bfloat162*)lo)[i*2]     = l01;
    ((__nv_bfloat162*)lo)[i*2 + 1] = l23;
}

// ---------------------------------------------------------------------------
// bf16x3 NT GEMM via mma.sync: 128x128 block, 4 warps, warp tile 64x64.
// Term-major MMA ordering (HH, HL, LH) to break accumulator RAW chains.
// Double-buffered cp.async, pitch-80B smem.
// MODE 0: QKV (A=x, B=w1) scatter to g_Q/g_K/g_Vt(bf16).  MODE 1: y @ w2 -> Cout.
// ---------------------------------------------------------------------------
#define T_AHI 0
#define T_ALO 10240
#define T_BHI 20480
#define T_BLO 30720
#define STAGE_BYTES 40960
#define GEMM_SMEM (2*STAGE_BYTES)

__device__ __forceinline__ void gemm_prefetch(uint32_t sdst,
    const __nv_bfloat16* a_hi, const __nv_bfloat16* a_lo,
    const __nv_bfloat16* b_hi, const __nv_bfloat16* b_lo)
{
    #pragma unroll
    for (int h = 0; h < 4; h++) {
        CP16(sdst + T_AHI + h * 16, a_hi + h * 8);
        CP16(sdst + T_ALO + h * 16, a_lo + h * 8);
        CP16(sdst + T_BHI + h * 16, b_hi + h * 8);
        CP16(sdst + T_BLO + h * 16, b_lo + h * 8);
    }
}

__device__ __forceinline__ void scatter_qkv(int m, int n, float2 v)
{
    int which = n >> 10, c = n & 1023;
    int h = c >> 6, d = c & 63;
    int b = m >> 10, t = m & 1023, bh = b * NHEAD + h;
    if (which == 0) {
        *(float2*)&g_Q[((size_t)bh * Tt + t) * HDIM + d] = v;
    } else if (which == 1) {
        *(float2*)&g_K[((size_t)bh * Tt + t) * HDIM + d] = v;
    } else {
        size_t i0 = ((size_t)bh * HDIM + d) * Tt + t;
        __nv_bfloat16 h0 = __float2bfloat16(v.x);
        __nv_bfloat16 h1 = __float2bfloat16(v.y);
        g_Vthi[i0]      = h0;
        g_Vtlo[i0]      = __float2bfloat16(v.x - __bfloat162float(h0));
        g_Vthi[i0 + Tt] = h1;
        g_Vtlo[i0 + Tt] = __float2bfloat16(v.y - __bfloat162float(h1));
    }
}

template<int MODE>
__global__ __launch_bounds__(128, 2)
void gemm_bf16x3(const float* __restrict__ bias, float* __restrict__ Cout)
{
    extern __shared__ char smem[];
    const uint32_t sb = smem_u32(smem);
    const int tid  = threadIdx.x;
    const int lane = tid & 31, wid = tid >> 5;
    const int wm = wid >> 1, wn = wid & 1;          // 2 x 2 warp grid, 64x64 tiles
    const int m0 = blockIdx.y * 128, n0 = blockIdx.x * 128;

    const __nv_bfloat16* Ahi = (MODE == 0) ? g_xhi  : g_yhi;
    const __nv_bfloat16* Alo = (MODE == 0) ? g_xlo  : g_ylo;
    const __nv_bfloat16* Bhi = (MODE == 0) ? g_w1hi : g_w2hi;
    const __nv_bfloat16* Blo = (MODE == 0) ? g_w1lo : g_w2lo;

    // cp.async: one 128-element row (64B per piece) per thread
    const size_t gA = (size_t)(m0 + tid) * Cc;
    const size_t gB = (size_t)(n0 + tid) * Cc;
    const uint32_t sOff = (uint32_t)tid * 80;

    // ldmatrix lane geometry
    const int jq = lane >> 3, rr = lane & 7;
    const int aRow  = wm * 64 + (jq & 1) * 8 + rr;   // + mf*16
    const int aColB = (jq >> 1) * 16;                // + kk*32 (bytes)
    const int bRow  = wn * 64 + (jq >> 1) * 8 + rr;  // + pf*16
    const int bColB = (jq & 1) * 16;

    float acc[4][8][4];
    #pragma unroll
    for (int i = 0; i < 4; i++)
        #pragma unroll
        for (int j = 0; j < 8; j++)
            #pragma unroll
            for (int e = 0; e < 4; e++) acc[i][j][e] = 0.0f;

    gemm_prefetch(sb + sOff, Ahi + gA, Alo + gA, Bhi + gB, Blo + gB);
    CP_COMMIT();

    for (int kt = 0; kt < KT; kt++) {
        const int cur = kt & 1;
        if (kt + 1 < KT) {
            const size_t ko = (size_t)(kt + 1) * 32;
            gemm_prefetch(sb + ((kt + 1) & 1) * STAGE_BYTES + sOff,
                          Ahi + gA + ko, Alo + gA + ko,
                          Bhi + gB + ko, Blo + gB + ko);
            CP_COMMIT();
            CP_WAIT1();
        } else {
            CP_WAIT0();
        }
        __syncthreads();

        const uint32_t base = sb + cur * STAGE_BYTES;
        #pragma unroll
        for (int kk = 0; kk < 2; kk++) {
            const uint32_t kB = kk * 32;
            uint32_t ah[4][4], al[4][4], bh[4][4], bl[4][4];
            #pragma unroll
            for (int mf = 0; mf < 4; mf++) {
                uint32_t addr = base + (uint32_t)(aRow + mf * 16) * 80 + aColB + kB;
                LDSM4(ah[mf][0], ah[mf][1], ah[mf][2], ah[mf][3], addr + T_AHI);
                LDSM4(al[mf][0], al[mf][1], al[mf][2], al[mf][3], addr + T_ALO);
            }
            #pragma unroll
            for (int pf = 0; pf < 4; pf++) {
                uint32_t addr = base + (uint32_t)(bRow + pf * 16) * 80 + bColB + kB;
                LDSM4(bh[pf][0], bh[pf][1], bh[pf][2], bh[pf][3], addr + T_BHI);
                LDSM4(bl[pf][0], bl[pf][1], bl[pf][2], bl[pf][3], addr + T_BLO);
            }
            // term-major ordering: 32 independent chains per pass
            #pragma unroll
            for (int mf = 0; mf < 4; mf++)
                #pragma unroll
                for (int nt = 0; nt < 8; nt++) {
                    const int pf = nt >> 1, ix = (nt & 1) * 2;
                    mma16816(acc[mf][nt], ah[mf], bh[pf][ix], bh[pf][ix + 1]);
                }
            #pragma unroll
            for (int mf = 0; mf < 4; mf++)
                #pragma unroll
                for (int nt = 0; nt < 8; nt++) {
                    const int pf = nt >> 1, ix = (nt & 1) * 2;
                    mma16816(acc[mf][nt], ah[mf], bl[pf][ix], bl[pf][ix + 1]);
                }
            #pragma unroll
            for (int mf = 0; mf < 4; mf++)
                #pragma unroll
                for (int nt = 0; nt < 8; nt++) {
                    const int pf = nt >> 1, ix = (nt & 1) * 2;
                    mma16816(acc[mf][nt], al[mf], bh[pf][ix], bh[pf][ix + 1]);
                }
        }
        __syncthreads();
    }

    // epilogue
    const int gid = lane >> 2, tg = lane & 3;
    #pragma unroll
    for (int mf = 0; mf < 4; mf++) {
        #pragma unroll
        for (int nt = 0; nt < 8; nt++) {
            const int n = n0 + wn * 64 + nt * 8 + tg * 2;
            const float2 bv = *(const float2*)&bias[n];
            const int mA = m0 + wm * 64 + mf * 16 + gid;
            float2 v01 = make_float2(acc[mf][nt][0] + bv.x, acc[mf][nt][1] + bv.y);
            float2 v23 = make_float2(acc[mf][nt][2] + bv.x, acc[mf][nt][3] + bv.y);
            if (MODE == 0) {
                scatter_qkv(mA,     n, v01);
                scatter_qkv(mA + 8, n, v23);
            } else {
                *(float2*)&Cout[(size_t)mA * Cc + n]       = v01;
                *(float2*)&Cout[(size_t)(mA + 8) * Cc + n] = v23;
            }
        }
    }
}

// ---------------------------------------------------------------------------
// RoPE: read fp32 g_Q/g_K, write bf16 hi/lo (Q pre-scaled by 0.125)
// ---------------------------------------------------------------------------
__global__ __launch_bounds__(256)
void rope_kernel()
{
    int idx = blockIdx.x * blockDim.x + threadIdx.x;
    int i  = idx & 31;
    int t  = (idx >> 5) & 1023;
    int bh = idx >> 15;

    float inv = expf(-(float)i * (logf(10000.0f) / 32.0f));
    float ang = (float)t * inv;
    float sv, cv;
    sincosf(ang, &sv, &cv);

    size_t base = (size_t)(bh * Tt + t) * HDIM + 2 * i;
    float x1 = g_Q[base], x2 = g_Q[base + 1];
    float q1 = (x1 * cv - x2 * sv) * 0.125f;
    float q2 = (x2 * cv + x1 * sv) * 0.125f;
    uint32_t hi, lo;
    split2(q1, q2, hi, lo);
    *(uint32_t*)&g_Qhi[base] = hi;
    *(uint32_t*)&g_Qlo[base] = lo;

    x1 = g_K[base]; x2 = g_K[base + 1];
    float k1 = x1 * cv - x2 * sv;
    float k2 = x2 * cv + x1 * sv;
    split2(k1, k2, hi, lo);
    *(uint32_t*)&g_Khi[base] = hi;
    *(uint32_t*)&g_Klo[base] = lo;
}

// ---------------------------------------------------------------------------
// Tensor-core flash attention (bf16x3), causal. Block = (qt, bh), 128 thr.
// ---------------------------------------------------------------------------
#define FPITCH 144
#define SQH 0
#define SQL 9216
#define SKH 18432
#define SKL 27648
#define SVH 36864
#define SVL 46080
#define FL_SMEM 55296

__global__ __launch_bounds__(128)
void flash_attn_kernel()
{
    extern __shared__ char smem[];
    const uint32_t sb = smem_u32(smem);
    const int tid  = threadIdx.x;
    const int lane = tid & 31, w = tid >> 5;
    const int qt = blockIdx.x;     // 0..15
    const int bh = blockIdx.y;     // 0..127

    const __nv_bfloat16* Qh = g_Qhi + ((size_t)bh * Tt + qt * 64) * HDIM;
    const __nv_bfloat16* Ql = g_Qlo + ((size_t)bh * Tt + qt * 64) * HDIM;
    const __nv_bfloat16* Kh = g_Khi + (size_t)bh * Tt * HDIM;
    const __nv_bfloat16* Kl = g_Klo + (size_t)bh * Tt * HDIM;
    const __nv_bfloat16* Vh = g_Vthi + (size_t)bh * HDIM * Tt;
    const __nv_bfloat16* Vl = g_Vtlo + (size_t)bh * HDIM * Tt;

    #pragma unroll
    for (int ii = 0; ii < 4; ii++) {
        int idx = tid + 128 * ii;
        int r = idx >> 3, c8 = (idx & 7) * 8;
        uint32_t so = (uint32_t)r * FPITCH + c8 * 2;
        *(uint4*)(smem + SQH + so) = *(const uint4*)&Qh[r * 64 + c8];
        *(uint4*)(smem + SQL + so) = *(const uint4*)&Ql[r * 64 + c8];
    }

    const int jq = lane >> 3, rr = lane & 7;
    const uint32_t aAddr = sb + (uint32_t)(w * 16 + (lane & 15)) * FPITCH
                         + (lane >> 4) * 16;
    const uint32_t bBase = (uint32_t)((jq >> 1) * 8 + rr) * FPITCH
                         + (jq & 1) * 16;

    const int gid = lane >> 2, tg = lane & 3;
    const int rowA = w * 16 + gid;
    const int rowB = rowA + 8;

    float o[8][4];
    #pragma unroll
    for (int nt = 0; nt < 8; nt++)
        #pragma unroll
        for (int e = 0; e < 4; e++) o[nt][e] = 0.0f;
    float mA = -1e30f, mB = -1e30f, lA = 0.0f, lB = 0.0f;

    for (int kt = 0; kt <= qt; kt++) {
        __syncthreads();
        #pragma unroll
        for (int ii = 0; ii < 4; ii++) {
            int idx = tid + 128 * ii;
            int r = idx >> 3, c8 = (idx & 7) * 8;
            uint32_t so = (uint32_t)r * FPITCH + c8 * 2;
            *(uint4*)(smem + SKH + so) = *(const uint4*)&Kh[(kt * 64 + r) * 64 + c8];
            *(uint4*)(smem + SKL + so) = *(const uint4*)&Kl[(kt * 64 + r) * 64 + c8];
            *(uint4*)(smem + SVH + so) = *(const uint4*)&Vh[(size_t)r * Tt + kt * 64 + c8];
            *(uint4*)(smem + SVL + so) = *(const uint4*)&Vl[(size_t)r * Tt + kt * 64 + c8];
        }
        __syncthreads();

        float c[8][4];
        #pragma unroll
        for (int nt = 0; nt < 8; nt++)
            #pragma unroll
            for (int e = 0; e < 4; e++) c[nt][e] = 0.0f;

        #pragma unroll
        for (int kk = 0; kk < 4; kk++) {
            uint32_t aH[4], aL[4];
            LDSM4(aH[0], aH[1], aH[2], aH[3], aAddr + SQH + kk * 32);
            LDSM4(aL[0], aL[1], aL[2], aL[3], aAddr + SQL + kk * 32);
            #pragma unroll
            for (int pf = 0; pf < 4; pf++) {
                uint32_t bH[4], bL[4];
                uint32_t ba = sb + bBase + (uint32_t)pf * 16 * FPITCH + kk * 32;
                LDSM4(bH[0], bH[1], bH[2], bH[3], ba + SKH);
                LDSM4(bL[0], bL[1], bL[2], bL[3], ba + SKL);
                const int nt0 = pf * 2;
                mma16816(c[nt0],     aH, bH[0], bH[1]);
                mma16816(c[nt0],     aH, bL[0], bL[1]);
                mma16816(c[nt0],     aL, bH[0], bH[1]);
                mma16816(c[nt0 + 1], aH, bH[2], bH[3]);
                mma16816(c[nt0 + 1], aH, bL[2], bL[3]);
                mma16816(c[nt0 + 1], aL, bH[2], bH[3]);
            }
        }

        if (kt == qt) {
            #pragma unroll
            for (int nt = 0; nt < 8; nt++) {
                const int colb = nt * 8 + tg * 2;
                if (colb     > rowA) c[nt][0] = -1e30f;
                if (colb + 1 > rowA) c[nt][1] = -1e30f;
                if (colb     > rowB) c[nt][2] = -1e30f;
                if (colb + 1 > rowB) c[nt][3] = -1e30f;
            }
        }

        float tmA = -1e30f, tmB = -1e30f;
        #pragma unroll
        for (int nt = 0; nt < 8; nt++) {
            tmA = fmaxf(tmA, fmaxf(c[nt][0], c[nt][1]));
            tmB = fmaxf(tmB, fmaxf(c[nt][2], c[nt][3]));
        }
        tmA = fmaxf(tmA, __shfl_xor_sync(0xffffffffu, tmA, 1));
        tmA = fmaxf(tmA, __shfl_xor_sync(0xffffffffu, tmA, 2));
        tmB = fmaxf(tmB, __shfl_xor_sync(0xffffffffu, tmB, 1));
        tmB = fmaxf(tmB, __shfl_xor_sync(0xffffffffu, tmB, 2));

        const float mnA = fmaxf(mA, tmA), mnB = fmaxf(mB, tmB);
        const float alA = __expf(mA - mnA), alB = __expf(mB - mnB);
        mA = mnA; mB = mnB;

        float sA = 0.0f, sB = 0.0f;
        #pragma unroll
        for (int nt = 0; nt < 8; nt++) {
            c[nt][0] = __expf(c[nt][0] - mnA); sA += c[nt][0];
            c[nt][1] = __expf(c[nt][1] - mnA); sA += c[nt][1];
            c[nt][2] = __expf(c[nt][2] - mnB); sB += c[nt][2];
            c[nt][3] = __expf(c[nt][3] - mnB); sB += c[nt][3];
        }
        sA += __shfl_xor_sync(0xffffffffu, sA, 1);
        sA += __shfl_xor_sync(0xffffffffu, sA, 2);
        sB += __shfl_xor_sync(0xffffffffu, sB, 1);
        sB += __shfl_xor_sync(0xffffffffu, sB, 2);
        lA = lA * alA + sA;
        lB = lB * alB + sB;
        #pragma unroll
        for (int nt = 0; nt < 8; nt++) {
            o[nt][0] *= alA; o[nt][1] *= alA;
            o[nt][2] *= alB; o[nt][3] *= alB;
        }

        #pragma unroll
        for (int ks = 0; ks < 4; ks++) {
            uint32_t pH[4], pL[4];
            split2(c[2*ks][0],     c[2*ks][1],     pH[0], pL[0]);
            split2(c[2*ks][2],     c[2*ks][3],     pH[1], pL[1]);
            split2(c[2*ks + 1][0], c[2*ks + 1][1], pH[2], pL[2]);
            split2(c[2*ks + 1][2], c[2*ks + 1][3], pH[3], pL[3]);
            #pragma unroll
            for (int pfd = 0; pfd < 4; pfd++) {
                uint32_t bH[4], bL[4];
                uint32_t ba = sb + bBase + (uint32_t)pfd * 16 * FPITCH + ks * 32;
                LDSM4(bH[0], bH[1], bH[2], bH[3], ba + SVH);
                LDSM4(bL[0], bL[1], bL[2], bL[3], ba + SVL);
                const int nd = pfd * 2;
                mma16816(o[nd],     pH, bH[0], bH[1]);
                mma16816(o[nd],     pH, bL[0], bL[1]);
                mma16816(o[nd],     pL, bH[0], bH[1]);
                mma16816(o[nd + 1], pH, bH[2], bH[3]);
                mma16816(o[nd + 1], pH, bL[2], bL[3]);
                mma16816(o[nd + 1], pL, bH[2], bH[3]);
            }
        }
    }

    const int b = bh >> 4, h = bh & 15;
    const float invA = 1.0f / lA, invB = 1.0f / lB;
    const size_t ybA = ((size_t)(b * Tt + qt * 64 + rowA)) * Cc + h * HDIM;
    const size_t ybB = ((size_t)(b * Tt + qt * 64 + rowB)) * Cc + h * HDIM;
    #pragma unroll
    for (int nt = 0; nt < 8; nt++) {
        const int d = nt * 8 + tg * 2;
        uint32_t hi, lo;
        split2(o[nt][0] * invA, o[nt][1] * invA, hi, lo);
        *(uint32_t*)&g_yhi[ybA + d] = hi;
        *(uint32_t*)&g_ylo[ybA + d] = lo;
        split2(o[nt][2] * invB, o[nt][3] * invB, hi, lo);
        *(uint32_t*)&g_yhi[ybB + d] = hi;
        *(uint32_t*)&g_ylo[ybB + d] = lo;
    }
}

// ---------------------------------------------------------------------------
extern "C" void kernel_launch(void* const* d_in, const int* in_sizes, int n_in,
                              void* d_out, int out_size)
{
    (void)in_sizes; (void)n_in; (void)out_size;
    const float* x   = (const float*)d_in[0];
    const float* ipw = (const float*)d_in[1];
    const float* ipb = (const float*)d_in[2];
    const float* opw = (const float*)d_in[3];
    const float* opb = (const float*)d_in[4];
    float* out = (float*)d_out;

    cudaFuncSetAttribute(gemm_bf16x3<0>,
                         cudaFuncAttributeMaxDynamicSharedMemorySize, GEMM_SMEM);
    cudaFuncSetAttribute(gemm_bf16x3<1>,
                         cudaFuncAttributeMaxDynamicSharedMemorySize, GEMM_SMEM);
    cudaFuncSetAttribute(flash_attn_kernel,
                         cudaFuncAttributeMaxDynamicSharedMemorySize, FL_SMEM);

    // 0) hi/lo bf16 conversions of x and weights
    cvt_kernel<0><<<(Mm*Cc/4 + 255)/256, 256>>>(x,   Mm*Cc/4);
    cvt_kernel<1><<<(N1*Cc/4 + 255)/256, 256>>>(ipw, N1*Cc/4);
    cvt_kernel<2><<<(Cc*Cc/4 + 255)/256, 256>>>(opw, Cc*Cc/4);

    // 1) QKV projection + bias; Q,K fp32 head-major; V -> bf16 hi/lo transposed
    {
        dim3 grid(N1 / 128, Mm / 128);
        gemm_bf16x3<0><<<grid, 128, GEMM_SMEM>>>(ipb, nullptr);
    }

    // 2) RoPE on Q, K -> bf16 hi/lo (Q scaled by 0.125)
    rope_kernel<<<(BHt * Tt * 32) / 256, 256>>>();

    // 3) tensor-core causal flash attention -> g_yhi/g_ylo
    {
        dim3 grid(Tt / 64, BHt);
        flash_attn_kernel<<<grid, 128, FL_SMEM>>>();
    }

    // 4) output projection + bias
    {
        dim3 grid(Cc / 128, Mm / 128);
        gemm_bf16x3<1><<<grid, 128, GEMM_SMEM>>>(opb, out);
    }
}

// round 7
// speedup vs baseline: 1.1173x; 1.1173x over previous
#include <cuda_runtime.h>
#include <cuda_bf16.h>
#include <math.h>
#include <stdint.h>

#define Bb 8
#define Tt 1024
#define Cc 1024
#define NHEAD 16
#define HDIM 64
#define BHt (Bb*NHEAD)     // 128
#define Mm (Bb*Tt)         // 8192
#define N1 (3*Cc)          // 3072
#define KT 32              // 1024/32 k-tiles

// ------------------------- device scratch (no allocs allowed) --------------
__device__ __nv_bfloat16 g_xhi[(size_t)Mm*Cc],  g_xlo[(size_t)Mm*Cc];
__device__ __nv_bfloat16 g_w1hi[(size_t)N1*Cc], g_w1lo[(size_t)N1*Cc];
__device__ __nv_bfloat16 g_w2hi[(size_t)Cc*Cc], g_w2lo[(size_t)Cc*Cc];
__device__ __nv_bfloat16 g_yhi[(size_t)Mm*Cc],  g_ylo[(size_t)Mm*Cc];
__device__ float g_Q [(size_t)BHt*Tt*HDIM];   // fp32 pre-rope [bh][t][d]
__device__ float g_K [(size_t)BHt*Tt*HDIM];
__device__ __nv_bfloat16 g_Qhi[(size_t)BHt*Tt*HDIM], g_Qlo[(size_t)BHt*Tt*HDIM]; // post-rope, x0.125
__device__ __nv_bfloat16 g_Khi[(size_t)BHt*Tt*HDIM], g_Klo[(size_t)BHt*Tt*HDIM];
__device__ __nv_bfloat16 g_Vthi[(size_t)BHt*HDIM*Tt], g_Vtlo[(size_t)BHt*HDIM*Tt]; // [bh][d][t]

// ------------------------------ PTX helpers --------------------------------
__device__ __forceinline__ uint32_t smem_u32(const void* p) {
    uint32_t a;
    asm("{ .reg .u64 t; cvta.to.shared.u64 t, %1; cvt.u32.u64 %0, t; }"
        : "=r"(a) : "l"(p));
    return a;
}

#define CP16(dst, src) \
    asm volatile("cp.async.cg.shared.global [%0], [%1], 16;" \
                 :: "r"(dst), "l"(src) : "memory")
#define CP_COMMIT() asm volatile("cp.async.commit_group;" ::: "memory")
#define CP_WAIT1()  asm volatile("cp.async.wait_group 1;" ::: "memory")
#define CP_WAIT0()  asm volatile("cp.async.wait_group 0;" ::: "memory")

#define LDSM4(r0, r1, r2, r3, a) \
    asm volatile("ldmatrix.sync.aligned.m8n8.x4.shared.b16 {%0,%1,%2,%3}, [%4];" \
                 : "=r"(r0), "=r"(r1), "=r"(r2), "=r"(r3) : "r"(a))

__device__ __forceinline__ void mma16816(float c[4], const uint32_t a[4],
                                         uint32_t b0, uint32_t b1) {
    asm volatile("mma.sync.aligned.m16n8k16.row.col.f32.bf16.bf16.f32 "
                 "{%0,%1,%2,%3}, {%4,%5,%6,%7}, {%8,%9}, {%0,%1,%2,%3};"
                 : "+f"(c[0]), "+f"(c[1]), "+f"(c[2]), "+f"(c[3])
                 : "r"(a[0]), "r"(a[1]), "r"(a[2]), "r"(a[3]),
                   "r"(b0), "r"(b1));
}

// two floats -> packed bf16x2 hi + residual lo
__device__ __forceinline__ void split2(float x, float y, uint32_t& hi, uint32_t& lo) {
    __nv_bfloat162 h = __floats2bfloat162_rn(x, y);
    float2 hf = __bfloat1622float2(h);
    __nv_bfloat162 l = __floats2bfloat162_rn(x - hf.x, y - hf.y);
    hi = *reinterpret_cast<uint32_t*>(&h);
    lo = *reinterpret_cast<uint32_t*>(&l);
}

// ---------------------------------------------------------------------------
// fp32 -> bf16 hi/lo split conversion
// ---------------------------------------------------------------------------
template<int W>
__global__ __launch_bounds__(256)
void cvt_kernel(const float* __restrict__ src, int n4)
{
    int i = blockIdx.x * blockDim.x + threadIdx.x;
    if (i >= n4) return;
    __nv_bfloat16* hi = (W == 0) ? g_xhi : (W == 1) ? g_w1hi : g_w2hi;
    __nv_bfloat16* lo = (W == 0) ? g_xlo : (W == 1) ? g_w1lo : g_w2lo;
    float4 v = ((const float4*)src)[i];
    __nv_bfloat162 h01 = __floats2bfloat162_rn(v.x, v.y);
    __nv_bfloat162 h23 = __floats2bfloat162_rn(v.z, v.w);
    float2 f01 = __bfloat1622float2(h01);
    float2 f23 = __bfloat1622float2(h23);
    __nv_bfloat162 l01 = __floats2bfloat162_rn(v.x - f01.x, v.y - f01.y);
    __nv_bfloat162 l23 = __floats2bfloat162_rn(v.z - f23.x, v.w - f23.y);
    ((__nv_bfloat162*)hi)[i*2]     = h01;
    ((__nv_bfloat162*)hi)[i*2 + 1] = h23;
    ((__nv_bfloat162*)lo)[i*2]     = l01;
    ((__nv_bfloat162*)lo)[i*2 + 1] = l23;
}

// ---------------------------------------------------------------------------
// bf16x3 NT GEMM via mma.sync: 128x128 block, 256 thr, 8 warps (2x4, 64x32).
// Term-major MMA ordering (16 HH, 16 HL, 16 LH per kk) to break RAW chains.
// Double-buffered cp.async, pitch-80B smem.
// ---------------------------------------------------------------------------
#define T_AHI 0
#define T_ALO 10240
#define T_BHI 20480
#define T_BLO 30720
#define STAGE_BYTES 40960
#define GEMM_SMEM (2*STAGE_BYTES)

__device__ __forceinline__ void gemm_prefetch(uint32_t sdst,
    const __nv_bfloat16* a_hi, const __nv_bfloat16* a_lo,
    const __nv_bfloat16* b_hi, const __nv_bfloat16* b_lo)
{
    CP16(sdst + T_AHI,      a_hi);
    CP16(sdst + T_AHI + 16, a_hi + 8);
    CP16(sdst + T_ALO,      a_lo);
    CP16(sdst + T_ALO + 16, a_lo + 8);
    CP16(sdst + T_BHI,      b_hi);
    CP16(sdst + T_BHI + 16, b_hi + 8);
    CP16(sdst + T_BLO,      b_lo);
    CP16(sdst + T_BLO + 16, b_lo + 8);
}

__device__ __forceinline__ void scatter_qkv(int m, int n, float2 v)
{
    int which = n >> 10, c = n & 1023;
    int h = c >> 6, d = c & 63;
    int b = m >> 10, t = m & 1023, bh = b * NHEAD + h;
    if (which == 0) {
        *(float2*)&g_Q[((size_t)bh * Tt + t) * HDIM + d] = v;
    } else if (which == 1) {
        *(float2*)&g_K[((size_t)bh * Tt + t) * HDIM + d] = v;
    } else {
        size_t i0 = ((size_t)bh * HDIM + d) * Tt + t;
        __nv_bfloat16 h0 = __float2bfloat16(v.x);
        __nv_bfloat16 h1 = __float2bfloat16(v.y);
        g_Vthi[i0]      = h0;
        g_Vtlo[i0]      = __float2bfloat16(v.x - __bfloat162float(h0));
        g_Vthi[i0 + Tt] = h1;
        g_Vtlo[i0 + Tt] = __float2bfloat16(v.y - __bfloat162float(h1));
    }
}

template<int MODE>
__global__ __launch_bounds__(256)
void gemm_bf16x3(const float* __restrict__ bias, float* __restrict__ Cout)
{
    extern __shared__ char smem[];
    const uint32_t sb = smem_u32(smem);
    const int tid  = threadIdx.x;
    const int lane = tid & 31, wid = tid >> 5;
    const int wm = wid >> 2, wn = wid & 3;         // 2 x 4 warp grid, 64x32 tiles
    const int m0 = blockIdx.y * 128, n0 = blockIdx.x * 128;

    const __nv_bfloat16* Ahi = (MODE == 0) ? g_xhi  : g_yhi;
    const __nv_bfloat16* Alo = (MODE == 0) ? g_xlo  : g_ylo;
    const __nv_bfloat16* Bhi = (MODE == 0) ? g_w1hi : g_w2hi;
    const __nv_bfloat16* Blo = (MODE == 0) ? g_w1lo : g_w2lo;

    const int lr = tid >> 1;
    const int lh = tid & 1;
    const size_t gA = (size_t)(m0 + lr) * Cc + lh * 16;
    const size_t gB = (size_t)(n0 + lr) * Cc + lh * 16;
    const uint32_t sOff = (uint32_t)lr * 80 + lh * 32;

    const int jq = lane >> 3, rr = lane & 7;
    const int aRow  = wm * 64 + (jq & 1) * 8 + rr;
    const int aColB = (jq >> 1) * 16;
    const int bRow  = wn * 32 + (jq >> 1) * 8 + rr;
    const int bColB = (jq & 1) * 16;

    float acc[4][4][4];
    #pragma unroll
    for (int i = 0; i < 4; i++)
        #pragma unroll
        for (int j = 0; j < 4; j++)
            #pragma unroll
            for (int e = 0; e < 4; e++) acc[i][j][e] = 0.0f;

    gemm_prefetch(sb + sOff, Ahi + gA, Alo + gA, Bhi + gB, Blo + gB);
    CP_COMMIT();

    for (int kt = 0; kt < KT; kt++) {
        const int cur = kt & 1;
        if (kt + 1 < KT) {
            const size_t ko = (size_t)(kt + 1) * 32;
            gemm_prefetch(sb + ((kt + 1) & 1) * STAGE_BYTES + sOff,
                          Ahi + gA + ko, Alo + gA + ko,
                          Bhi + gB + ko, Blo + gB + ko);
            CP_COMMIT();
            CP_WAIT1();
        } else {
            CP_WAIT0();
        }
        __syncthreads();

        const uint32_t base = sb + cur * STAGE_BYTES;
        #pragma unroll
        for (int kk = 0; kk < 2; kk++) {
            const uint32_t kB = kk * 32;
            uint32_t ah[4][4], al[4][4], bhr[2][4], blr[2][4];
            #pragma unroll
            for (int mf = 0; mf < 4; mf++) {
                uint32_t addr = base + (uint32_t)(aRow + mf * 16) * 80 + aColB + kB;
                LDSM4(ah[mf][0], ah[mf][1], ah[mf][2], ah[mf][3], addr + T_AHI);
                LDSM4(al[mf][0], al[mf][1], al[mf][2], al[mf][3], addr + T_ALO);
            }
            #pragma unroll
            for (int pf = 0; pf < 2; pf++) {
                uint32_t addr = base + (uint32_t)(bRow + pf * 16) * 80 + bColB + kB;
                LDSM4(bhr[pf][0], bhr[pf][1], bhr[pf][2], bhr[pf][3], addr + T_BHI);
                LDSM4(blr[pf][0], blr[pf][1], blr[pf][2], blr[pf][3], addr + T_BLO);
            }
            // term-major: 16 independent accumulator chains per pass
            #pragma unroll
            for (int mf = 0; mf < 4; mf++)
                #pragma unroll
                for (int nt = 0; nt < 4; nt++) {
                    const int pf = nt >> 1, ix = (nt & 1) * 2;
                    mma16816(acc[mf][nt], ah[mf], bhr[pf][ix], bhr[pf][ix + 1]);
                }
            #pragma unroll
            for (int mf = 0; mf < 4; mf++)
                #pragma unroll
                for (int nt = 0; nt < 4; nt++) {
                    const int pf = nt >> 1, ix = (nt & 1) * 2;
                    mma16816(acc[mf][nt], ah[mf], blr[pf][ix], blr[pf][ix + 1]);
                }
            #pragma unroll
            for (int mf = 0; mf < 4; mf++)
                #pragma unroll
                for (int nt = 0; nt < 4; nt++) {
                    const int pf = nt >> 1, ix = (nt & 1) * 2;
                    mma16816(acc[mf][nt], al[mf], bhr[pf][ix], bhr[pf][ix + 1]);
                }
        }
        __syncthreads();
    }

    const int gid = lane >> 2, tg = lane & 3;
    #pragma unroll
    for (int mf = 0; mf < 4; mf++) {
        #pragma unroll
        for (int nt = 0; nt < 4; nt++) {
            const int n = n0 + wn * 32 + nt * 8 + tg * 2;
            const float2 bv = *(const float2*)&bias[n];
            const int mA = m0 + wm * 64 + mf * 16 + gid;
            float2 v01 = make_float2(acc[mf][nt][0] + bv.x, acc[mf][nt][1] + bv.y);
            float2 v23 = make_float2(acc[mf][nt][2] + bv.x, acc[mf][nt][3] + bv.y);
            if (MODE == 0) {
                scatter_qkv(mA,     n, v01);
                scatter_qkv(mA + 8, n, v23);
            } else {
                *(float2*)&Cout[(size_t)mA * Cc + n]       = v01;
                *(float2*)&Cout[(size_t)(mA + 8) * Cc + n] = v23;
            }
        }
    }
}

// ---------------------------------------------------------------------------
// RoPE: read fp32 g_Q/g_K, write bf16 hi/lo (Q pre-scaled by 0.125)
// ---------------------------------------------------------------------------
__global__ __launch_bounds__(256)
void rope_kernel()
{
    int idx = blockIdx.x * blockDim.x + threadIdx.x;
    int i  = idx & 31;
    int t  = (idx >> 5) & 1023;
    int bh = idx >> 15;

    float inv = expf(-(float)i * (logf(10000.0f) / 32.0f));
    float ang = (float)t * inv;
    float sv, cv;
    sincosf(ang, &sv, &cv);

    size_t base = (size_t)(bh * Tt + t) * HDIM + 2 * i;
    float x1 = g_Q[base], x2 = g_Q[base + 1];
    float q1 = (x1 * cv - x2 * sv) * 0.125f;
    float q2 = (x2 * cv + x1 * sv) * 0.125f;
    uint32_t hi, lo;
    split2(q1, q2, hi, lo);
    *(uint32_t*)&g_Qhi[base] = hi;
    *(uint32_t*)&g_Qlo[base] = lo;

    x1 = g_K[base]; x2 = g_K[base + 1];
    float k1 = x1 * cv - x2 * sv;
    float k2 = x2 * cv + x1 * sv;
    split2(k1, k2, hi, lo);
    *(uint32_t*)&g_Khi[base] = hi;
    *(uint32_t*)&g_Klo[base] = lo;
}

// ---------------------------------------------------------------------------
// Tensor-core flash attention (bf16x3), causal. Block = (qt, bh), 128 thr.
// ---------------------------------------------------------------------------
#define FPITCH 144
#define SQH 0
#define SQL 9216
#define SKH 18432
#define SKL 27648
#define SVH 36864
#define SVL 46080
#define FL_SMEM 55296

__global__ __launch_bounds__(128)
void flash_attn_kernel()
{
    extern __shared__ char smem[];
    const uint32_t sb = smem_u32(smem);
    const int tid  = threadIdx.x;
    const int lane = tid & 31, w = tid >> 5;
    const int qt = blockIdx.x;     // 0..15
    const int bh = blockIdx.y;     // 0..127

    const __nv_bfloat16* Qh = g_Qhi + ((size_t)bh * Tt + qt * 64) * HDIM;
    const __nv_bfloat16* Ql = g_Qlo + ((size_t)bh * Tt + qt * 64) * HDIM;
    const __nv_bfloat16* Kh = g_Khi + (size_t)bh * Tt * HDIM;
    const __nv_bfloat16* Kl = g_Klo + (size_t)bh * Tt * HDIM;
    const __nv_bfloat16* Vh = g_Vthi + (size_t)bh * HDIM * Tt;
    const __nv_bfloat16* Vl = g_Vtlo + (size_t)bh * HDIM * Tt;

    #pragma unroll
    for (int ii = 0; ii < 4; ii++) {
        int idx = tid + 128 * ii;
        int r = idx >> 3, c8 = (idx & 7) * 8;
        uint32_t so = (uint32_t)r * FPITCH + c8 * 2;
        *(uint4*)(smem + SQH + so) = *(const uint4*)&Qh[r * 64 + c8];
        *(uint4*)(smem + SQL + so) = *(const uint4*)&Ql[r * 64 + c8];
    }

    const int jq = lane >> 3, rr = lane & 7;
    const uint32_t aAddr = sb + (uint32_t)(w * 16 + (lane & 15)) * FPITCH
                         + (lane >> 4) * 16;
    const uint32_t bBase = (uint32_t)((jq >> 1) * 8 + rr) * FPITCH
                         + (jq & 1) * 16;

    const int gid = lane >> 2, tg = lane & 3;
    const int rowA = w * 16 + gid;
    const int rowB = rowA + 8;

    float o[8][4];
    #pragma unroll
    for (int nt = 0; nt < 8; nt++)
        #pragma unroll
        for (int e = 0; e < 4; e++) o[nt][e] = 0.0f;
    float mA = -1e30f, mB = -1e30f, lA = 0.0f, lB = 0.0f;

    for (int kt = 0; kt <= qt; kt++) {
        __syncthreads();
        #pragma unroll
        for (int ii = 0; ii < 4; ii++) {
            int idx = tid + 128 * ii;
            int r = idx >> 3, c8 = (idx & 7) * 8;
            uint32_t so = (uint32_t)r * FPITCH + c8 * 2;
            *(uint4*)(smem + SKH + so) = *(const uint4*)&Kh[(kt * 64 + r) * 64 + c8];
            *(uint4*)(smem + SKL + so) = *(const uint4*)&Kl[(kt * 64 + r) * 64 + c8];
            *(uint4*)(smem + SVH + so) = *(const uint4*)&Vh[(size_t)r * Tt + kt * 64 + c8];
            *(uint4*)(smem + SVL + so) = *(const uint4*)&Vl[(size_t)r * Tt + kt * 64 + c8];
        }
        __syncthreads();

        float c[8][4];
        #pragma unroll
        for (int nt = 0; nt < 8; nt++)
            #pragma unroll
            for (int e = 0; e < 4; e++) c[nt][e] = 0.0f;

        #pragma unroll
        for (int kk = 0; kk < 4; kk++) {
            uint32_t aH[4], aL[4];
            LDSM4(aH[0], aH[1], aH[2], aH[3], aAddr + SQH + kk * 32);
            LDSM4(aL[0], aL[1], aL[2], aL[3], aAddr + SQL + kk * 32);
            #pragma unroll
            for (int pf = 0; pf < 4; pf++) {
                uint32_t bH[4], bL[4];
                uint32_t ba = sb + bBase + (uint32_t)pf * 16 * FPITCH + kk * 32;
                LDSM4(bH[0], bH[1], bH[2], bH[3], ba + SKH);
                LDSM4(bL[0], bL[1], bL[2], bL[3], ba + SKL);
                const int nt0 = pf * 2;
                mma16816(c[nt0],     aH, bH[0], bH[1]);
                mma16816(c[nt0 + 1], aH, bH[2], bH[3]);
                mma16816(c[nt0],     aH, bL[0], bL[1]);
                mma16816(c[nt0 + 1], aH, bL[2], bL[3]);
                mma16816(c[nt0],     aL, bH[0], bH[1]);
                mma16816(c[nt0 + 1], aL, bH[2], bH[3]);
            }
        }

        if (kt == qt) {
            #pragma unroll
            for (int nt = 0; nt < 8; nt++) {
                const int colb = nt * 8 + tg * 2;
                if (colb     > rowA) c[nt][0] = -1e30f;
                if (colb + 1 > rowA) c[nt][1] = -1e30f;
                if (colb     > rowB) c[nt][2] = -1e30f;
                if (colb + 1 > rowB) c[nt][3] = -1e30f;
            }
        }

        float tmA = -1e30f, tmB = -1e30f;
        #pragma unroll
        for (int nt = 0; nt < 8; nt++) {
            tmA = fmaxf(tmA, fmaxf(c[nt][0], c[nt][1]));
            tmB = fmaxf(tmB, fmaxf(c[nt][2], c[nt][3]));
        }
        tmA = fmaxf(tmA, __shfl_xor_sync(0xffffffffu, tmA, 1));
        tmA = fmaxf(tmA, __shfl_xor_sync(0xffffffffu, tmA, 2));
        tmB = fmaxf(tmB, __shfl_xor_sync(0xffffffffu, tmB, 1));
        tmB = fmaxf(tmB, __shfl_xor_sync(0xffffffffu, tmB, 2));

        const float mnA = fmaxf(mA, tmA), mnB = fmaxf(mB, tmB);
        const float alA = __expf(mA - mnA), alB = __expf(mB - mnB);
        mA = mnA; mB = mnB;

        float sA = 0.0f, sB = 0.0f;
        #pragma unroll
        for (int nt = 0; nt < 8; nt++) {
            c[nt][0] = __expf(c[nt][0] - mnA); sA += c[nt][0];
            c[nt][1] = __expf(c[nt][1] - mnA); sA += c[nt][1];
            c[nt][2] = __expf(c[nt][2] - mnB); sB += c[nt][2];
            c[nt][3] = __expf(c[nt][3] - mnB); sB += c[nt][3];
        }
        sA += __shfl_xor_sync(0xffffffffu, sA, 1);
        sA += __shfl_xor_sync(0xffffffffu, sA, 2);
        sB += __shfl_xor_sync(0xffffffffu, sB, 1);
        sB += __shfl_xor_sync(0xffffffffu, sB, 2);
        lA = lA * alA + sA;
        lB = lB * alB + sB;
        #pragma unroll
        for (int nt = 0; nt < 8; nt++) {
            o[nt][0] *= alA; o[nt][1] *= alA;
            o[nt][2] *= alB; o[nt][3] *= alB;
        }

        #pragma unroll
        for (int ks = 0; ks < 4; ks++) {
            uint32_t pH[4], pL[4];
            split2(c[2*ks][0],     c[2*ks][1],     pH[0], pL[0]);
            split2(c[2*ks][2],     c[2*ks][3],     pH[1], pL[1]);
            split2(c[2*ks + 1][0], c[2*ks + 1][1], pH[2], pL[2]);
            split2(c[2*ks + 1][2], c[2*ks + 1][3], pH[3], pL[3]);
            #pragma unroll
            for (int pfd = 0; pfd < 4; pfd++) {
                uint32_t bH[4], bL[4];
                uint32_t ba = sb + bBase + (uint32_t)pfd * 16 * FPITCH + ks * 32;
                LDSM4(bH[0], bH[1], bH[2], bH[3], ba + SVH);
                LDSM4(bL[0], bL[1], bL[2], bL[3], ba + SVL);
                const int nd = pfd * 2;
                mma16816(o[nd],     pH, bH[0], bH[1]);
                mma16816(o[nd + 1], pH, bH[2], bH[3]);
                mma16816(o[nd],     pH, bL[0], bL[1]);
                mma16816(o[nd + 1], pH, bL[2], bL[3]);
                mma16816(o[nd],     pL, bH[0], bH[1]);
                mma16816(o[nd + 1], pL, bH[2], bH[3]);
            }
        }
    }

    const int b = bh >> 4, h = bh & 15;
    const float invA = 1.0f / lA, invB = 1.0f / lB;
    const size_t ybA = ((size_t)(b * Tt + qt * 64 + rowA)) * Cc + h * HDIM;
    const size_t ybB = ((size_t)(b * Tt + qt * 64 + rowB)) * Cc + h * HDIM;
    #pragma unroll
    for (int nt = 0; nt < 8; nt++) {
        const int d = nt * 8 + tg * 2;
        uint32_t hi, lo;
        split2(o[nt][0] * invA, o[nt][1] * invA, hi, lo);
        *(uint32_t*)&g_yhi[ybA + d] = hi;
        *(uint32_t*)&g_ylo[ybA + d] = lo;
        split2(o[nt][2] * invB, o[nt][3] * invB, hi, lo);
        *(uint32_t*)&g_yhi[ybB + d] = hi;
        *(uint32_t*)&g_ylo[ybB + d] = lo;
    }
}

// ---------------------------------------------------------------------------
extern "C" void kernel_launch(void* const* d_in, const int* in_sizes, int n_in,
                              void* d_out, int out_size)
{
    (void)in_sizes; (void)n_in; (void)out_size;
    const float* x   = (const float*)d_in[0];
    const float* ipw = (const float*)d_in[1];
    const float* ipb = (const float*)d_in[2];
    const float* opw = (const float*)d_in[3];
    const float* opb = (const float*)d_in[4];
    float* out = (float*)d_out;

    cudaFuncSetAttribute(gemm_bf16x3<0>,
                         cudaFuncAttributeMaxDynamicSharedMemorySize, GEMM_SMEM);
    cudaFuncSetAttribute(gemm_bf16x3<1>,
                         cudaFuncAttributeMaxDynamicSharedMemorySize, GEMM_SMEM);
    cudaFuncSetAttribute(flash_attn_kernel,
                         cudaFuncAttributeMaxDynamicSharedMemorySize, FL_SMEM);

    // 0) hi/lo bf16 conversions of x and weights
    cvt_kernel<0><<<(Mm*Cc/4 + 255)/256, 256>>>(x,   Mm*Cc/4);
    cvt_kernel<1><<<(N1*Cc/4 + 255)/256, 256>>>(ipw, N1*Cc/4);
    cvt_kernel<2><<<(Cc*Cc/4 + 255)/256, 256>>>(opw, Cc*Cc/4);

    // 1) QKV projection + bias; Q,K fp32 head-major; V -> bf16 hi/lo transposed
    {
        dim3 grid(N1 / 128, Mm / 128);
        gemm_bf16x3<0><<<grid, 256, GEMM_SMEM>>>(ipb, nullptr);
    }

    // 2) RoPE on Q, K -> bf16 hi/lo (Q scaled by 0.125)
    rope_kernel<<<(BHt * Tt * 32) / 256, 256>>>();

    // 3) tensor-core causal flash attention -> g_yhi/g_ylo
    {
        dim3 grid(Tt / 64, BHt);
        flash_attn_kernel<<<grid, 128, FL_SMEM>>>();
    }

    // 4) output projection + bias  (256 threads — R6's 128 was the NaN bug)
    {
        dim3 grid(Cc / 128, Mm / 128);
        gemm_bf16x3<1><<<grid, 256, GEMM_SMEM>>>(opb, out);
    }
}

// round 8
// speedup vs baseline: 1.1862x; 1.0616x over previous
#include <cuda_runtime.h>
#include <cuda_bf16.h>
#include <math.h>
#include <stdint.h>

#define Bb 8
#define Tt 1024
#define Cc 1024
#define NHEAD 16
#define HDIM 64
#define BHt (Bb*NHEAD)     // 128
#define Mm (Bb*Tt)         // 8192
#define N1 (3*Cc)          // 3072
#define KT 32              // 1024/32 k-tiles

// ------------------------- device scratch (no allocs allowed) --------------
__device__ __nv_bfloat16 g_xhi[(size_t)Mm*Cc],  g_xlo[(size_t)Mm*Cc];
__device__ __nv_bfloat16 g_w1hi[(size_t)N1*Cc], g_w1lo[(size_t)N1*Cc];
__device__ __nv_bfloat16 g_w2hi[(size_t)Cc*Cc], g_w2lo[(size_t)Cc*Cc];
__device__ __nv_bfloat16 g_yhi[(size_t)Mm*Cc],  g_ylo[(size_t)Mm*Cc];
__device__ __nv_bfloat16 g_Qhi[(size_t)BHt*Tt*HDIM], g_Qlo[(size_t)BHt*Tt*HDIM]; // post-rope, x0.125
__device__ __nv_bfloat16 g_Khi[(size_t)BHt*Tt*HDIM], g_Klo[(size_t)BHt*Tt*HDIM]; // post-rope
__device__ __nv_bfloat16 g_Vthi[(size_t)BHt*HDIM*Tt], g_Vtlo[(size_t)BHt*HDIM*Tt]; // [bh][d][t]

// ------------------------------ PTX helpers --------------------------------
__device__ __forceinline__ uint32_t smem_u32(const void* p) {
    uint32_t a;
    asm("{ .reg .u64 t; cvta.to.shared.u64 t, %1; cvt.u32.u64 %0, t; }"
        : "=r"(a) : "l"(p));
    return a;
}

#define CP16(dst, src) \
    asm volatile("cp.async.cg.shared.global [%0], [%1], 16;" \
                 :: "r"(dst), "l"(src) : "memory")
#define CP_COMMIT() asm volatile("cp.async.commit_group;" ::: "memory")
#define CP_WAIT1()  asm volatile("cp.async.wait_group 1;" ::: "memory")
#define CP_WAIT0()  asm volatile("cp.async.wait_group 0;" ::: "memory")

#define LDSM4(r0, r1, r2, r3, a) \
    asm volatile("ldmatrix.sync.aligned.m8n8.x4.shared.b16 {%0,%1,%2,%3}, [%4];" \
                 : "=r"(r0), "=r"(r1), "=r"(r2), "=r"(r3) : "r"(a))

__device__ __forceinline__ void mma16816(float c[4], const uint32_t a[4],
                                         uint32_t b0, uint32_t b1) {
    asm volatile("mma.sync.aligned.m16n8k16.row.col.f32.bf16.bf16.f32 "
                 "{%0,%1,%2,%3}, {%4,%5,%6,%7}, {%8,%9}, {%0,%1,%2,%3};"
                 : "+f"(c[0]), "+f"(c[1]), "+f"(c[2]), "+f"(c[3])
                 : "r"(a[0]), "r"(a[1]), "r"(a[2]), "r"(a[3]),
                   "r"(b0), "r"(b1));
}

// two floats -> packed bf16x2 hi + residual lo
__device__ __forceinline__ void split2(float x, float y, uint32_t& hi, uint32_t& lo) {
    __nv_bfloat162 h = __floats2bfloat162_rn(x, y);
    float2 hf = __bfloat1622float2(h);
    __nv_bfloat162 l = __floats2bfloat162_rn(x - hf.x, y - hf.y);
    hi = *reinterpret_cast<uint32_t*>(&h);
    lo = *reinterpret_cast<uint32_t*>(&l);
}

// ---------------------------------------------------------------------------
// fp32 -> bf16 hi/lo split conversion
// ---------------------------------------------------------------------------
template<int W>
__global__ __launch_bounds__(256)
void cvt_kernel(const float* __restrict__ src, int n4)
{
    int i = blockIdx.x * blockDim.x + threadIdx.x;
    if (i >= n4) return;
    __nv_bfloat16* hi = (W == 0) ? g_xhi : (W == 1) ? g_w1hi : g_w2hi;
    __nv_bfloat16* lo = (W == 0) ? g_xlo : (W == 1) ? g_w1lo : g_w2lo;
    float4 v = ((const float4*)src)[i];
    __nv_bfloat162 h01 = __floats2bfloat162_rn(v.x, v.y);
    __nv_bfloat162 h23 = __floats2bfloat162_rn(v.z, v.w);
    float2 f01 = __bfloat1622float2(h01);
    float2 f23 = __bfloat1622float2(h23);
    __nv_bfloat162 l01 = __floats2bfloat162_rn(v.x - f01.x, v.y - f01.y);
    __nv_bfloat162 l23 = __floats2bfloat162_rn(v.z - f23.x, v.w - f23.y);
    ((__nv_bfloat162*)hi)[i*2]     = h01;
    ((__nv_bfloat162*)hi)[i*2 + 1] = h23;
    ((__nv_bfloat162*)lo)[i*2]     = l01;
    ((__nv_bfloat162*)lo)[i*2 + 1] = l23;
}

// ---------------------------------------------------------------------------
// bf16x3 NT GEMM via mma.sync (R4 config: 256 thr, 8 warps 2x4, 64x32 tiles,
// interleaved MMA ordering). MODE 0 epilogue applies RoPE to Q/K in-register
// and stores bf16 hi/lo directly; V stored transposed bf16 hi/lo.
// ---------------------------------------------------------------------------
#define T_AHI 0
#define T_ALO 10240
#define T_BHI 20480
#define T_BLO 30720
#define STAGE_BYTES 40960
#define GEMM_SMEM (2*STAGE_BYTES)

#define ROPE_LN_OVER_32 0.2878231366242557f   // ln(10000)/32

__device__ __forceinline__ void gemm_prefetch(uint32_t sdst,
    const __nv_bfloat16* a_hi, const __nv_bfloat16* a_lo,
    const __nv_bfloat16* b_hi, const __nv_bfloat16* b_lo)
{
    CP16(sdst + T_AHI,      a_hi);
    CP16(sdst + T_AHI + 16, a_hi + 8);
    CP16(sdst + T_ALO,      a_lo);
    CP16(sdst + T_ALO + 16, a_lo + 8);
    CP16(sdst + T_BHI,      b_hi);
    CP16(sdst + T_BHI + 16, b_hi + 8);
    CP16(sdst + T_BLO,      b_lo);
    CP16(sdst + T_BLO + 16, b_lo + 8);
}

// Epilogue scatter with fused RoPE. v = (col d, col d+1), d even.
__device__ __forceinline__ void scatter_qkv(int m, int n, float2 v)
{
    const int which = n >> 10, c = n & 1023;
    const int h = c >> 6, d = c & 63;
    const int b = m >> 10, t = m & 1023, bh = b * NHEAD + h;
    if (which == 2) {
        size_t i0 = ((size_t)bh * HDIM + d) * Tt + t;
        __nv_bfloat16 h0 = __float2bfloat16(v.x);
        __nv_bfloat16 h1 = __float2bfloat16(v.y);
        g_Vthi[i0]      = h0;
        g_Vtlo[i0]      = __float2bfloat16(v.x - __bfloat162float(h0));
        g_Vthi[i0 + Tt] = h1;
        g_Vtlo[i0 + Tt] = __float2bfloat16(v.y - __bfloat162float(h1));
        return;
    }
    // RoPE rotation for pair index i = d/2
    const float inv = expf(-(float)(d >> 1) * ROPE_LN_OVER_32);
    float sv, cv;
    sincosf((float)t * inv, &sv, &cv);
    float r1 = v.x * cv - v.y * sv;
    float r2 = v.y * cv + v.x * sv;
    const size_t base = ((size_t)bh * Tt + t) * HDIM + d;
    uint32_t hi, lo;
    if (which == 0) {
        split2(r1 * 0.125f, r2 * 0.125f, hi, lo);   // Q pre-scaled 1/sqrt(hd)
        *(uint32_t*)&g_Qhi[base] = hi;
        *(uint32_t*)&g_Qlo[base] = lo;
    } else {
        split2(r1, r2, hi, lo);
        *(uint32_t*)&g_Khi[base] = hi;
        *(uint32_t*)&g_Klo[base] = lo;
    }
}

template<int MODE>
__global__ __launch_bounds__(256)
void gemm_bf16x3(const float* __restrict__ bias, float* __restrict__ Cout)
{
    extern __shared__ char smem[];
    const uint32_t sb = smem_u32(smem);
    const int tid  = threadIdx.x;
    const int lane = tid & 31, wid = tid >> 5;
    const int wm = wid >> 2, wn = wid & 3;         // 2 x 4 warp grid, 64x32 tiles
    const int m0 = blockIdx.y * 128, n0 = blockIdx.x * 128;

    const __nv_bfloat16* Ahi = (MODE == 0) ? g_xhi  : g_yhi;
    const __nv_bfloat16* Alo = (MODE == 0) ? g_xlo  : g_ylo;
    const __nv_bfloat16* Bhi = (MODE == 0) ? g_w1hi : g_w2hi;
    const __nv_bfloat16* Blo = (MODE == 0) ? g_w1lo : g_w2lo;

    const int lr = tid >> 1;
    const int lh = tid & 1;
    const size_t gA = (size_t)(m0 + lr) * Cc + lh * 16;
    const size_t gB = (size_t)(n0 + lr) * Cc + lh * 16;
    const uint32_t sOff = (uint32_t)lr * 80 + lh * 32;

    const int jq = lane >> 3, rr = lane & 7;
    const int aRow  = wm * 64 + (jq & 1) * 8 + rr;
    const int aColB = (jq >> 1) * 16;
    const int bRow  = wn * 32 + (jq >> 1) * 8 + rr;
    const int bColB = (jq & 1) * 16;

    float acc[4][4][4];
    #pragma unroll
    for (int i = 0; i < 4; i++)
        #pragma unroll
        for (int j = 0; j < 4; j++)
            #pragma unroll
            for (int e = 0; e < 4; e++) acc[i][j][e] = 0.0f;

    gemm_prefetch(sb + sOff, Ahi + gA, Alo + gA, Bhi + gB, Blo + gB);
    CP_COMMIT();

    for (int kt = 0; kt < KT; kt++) {
        const int cur = kt & 1;
        if (kt + 1 < KT) {
            const size_t ko = (size_t)(kt + 1) * 32;
            gemm_prefetch(sb + ((kt + 1) & 1) * STAGE_BYTES + sOff,
                          Ahi + gA + ko, Alo + gA + ko,
                          Bhi + gB + ko, Blo + gB + ko);
            CP_COMMIT();
            CP_WAIT1();
        } else {
            CP_WAIT0();
        }
        __syncthreads();

        const uint32_t base = sb + cur * STAGE_BYTES;
        #pragma unroll
        for (int kk = 0; kk < 2; kk++) {
            const uint32_t kB = kk * 32;
            uint32_t ah[4][4], al[4][4], bhr[2][4], blr[2][4];
            #pragma unroll
            for (int mf = 0; mf < 4; mf++) {
                uint32_t addr = base + (uint32_t)(aRow + mf * 16) * 80 + aColB + kB;
                LDSM4(ah[mf][0], ah[mf][1], ah[mf][2], ah[mf][3], addr + T_AHI);
                LDSM4(al[mf][0], al[mf][1], al[mf][2], al[mf][3], addr + T_ALO);
            }
            #pragma unroll
            for (int pf = 0; pf < 2; pf++) {
                uint32_t addr = base + (uint32_t)(bRow + pf * 16) * 80 + bColB + kB;
                LDSM4(bhr[pf][0], bhr[pf][1], bhr[pf][2], bhr[pf][3], addr + T_BHI);
                LDSM4(blr[pf][0], blr[pf][1], blr[pf][2], blr[pf][3], addr + T_BLO);
            }
            #pragma unroll
            for (int mf = 0; mf < 4; mf++) {
                #pragma unroll
                for (int nt = 0; nt < 4; nt++) {
                    const int pf = nt >> 1, ix = (nt & 1) * 2;
                    mma16816(acc[mf][nt], ah[mf], bhr[pf][ix], bhr[pf][ix + 1]);
                    mma16816(acc[mf][nt], ah[mf], blr[pf][ix], blr[pf][ix + 1]);
                    mma16816(acc[mf][nt], al[mf], bhr[pf][ix], bhr[pf][ix + 1]);
                }
            }
        }
        __syncthreads();
    }

    const int gid = lane >> 2, tg = lane & 3;
    #pragma unroll
    for (int mf = 0; mf < 4; mf++) {
        #pragma unroll
        for (int nt = 0; nt < 4; nt++) {
            const int n = n0 + wn * 32 + nt * 8 + tg * 2;
            const float2 bv = *(const float2*)&bias[n];
            const int mA = m0 + wm * 64 + mf * 16 + gid;
            float2 v01 = make_float2(acc[mf][nt][0] + bv.x, acc[mf][nt][1] + bv.y);
            float2 v23 = make_float2(acc[mf][nt][2] + bv.x, acc[mf][nt][3] + bv.y);
            if (MODE == 0) {
                scatter_qkv(mA,     n, v01);
                scatter_qkv(mA + 8, n, v23);
            } else {
                *(float2*)&Cout[(size_t)mA * Cc + n]       = v01;
                *(float2*)&Cout[(size_t)(mA + 8) * Cc + n] = v23;
            }
        }
    }
}

// ---------------------------------------------------------------------------
// Tensor-core flash attention (bf16x3), causal. Block = (qt, bh), 128 thr.
// (R4 configuration)
// ---------------------------------------------------------------------------
#define FPITCH 144
#define SQH 0
#define SQL 9216
#define SKH 18432
#define SKL 27648
#define SVH 36864
#define SVL 46080
#define FL_SMEM 55296

__global__ __launch_bounds__(128)
void flash_attn_kernel()
{
    extern __shared__ char smem[];
    const uint32_t sb = smem_u32(smem);
    const int tid  = threadIdx.x;
    const int lane = tid & 31, w = tid >> 5;
    const int qt = blockIdx.x;     // 0..15
    const int bh = blockIdx.y;     // 0..127

    const __nv_bfloat16* Qh = g_Qhi + ((size_t)bh * Tt + qt * 64) * HDIM;
    const __nv_bfloat16* Ql = g_Qlo + ((size_t)bh * Tt + qt * 64) * HDIM;
    const __nv_bfloat16* Kh = g_Khi + (size_t)bh * Tt * HDIM;
    const __nv_bfloat16* Kl = g_Klo + (size_t)bh * Tt * HDIM;
    const __nv_bfloat16* Vh = g_Vthi + (size_t)bh * HDIM * Tt;
    const __nv_bfloat16* Vl = g_Vtlo + (size_t)bh * HDIM * Tt;

    #pragma unroll
    for (int ii = 0; ii < 4; ii++) {
        int idx = tid + 128 * ii;
        int r = idx >> 3, c8 = (idx & 7) * 8;
        uint32_t so = (uint32_t)r * FPITCH + c8 * 2;
        *(uint4*)(smem + SQH + so) = *(const uint4*)&Qh[r * 64 + c8];
        *(uint4*)(smem + SQL + so) = *(const uint4*)&Ql[r * 64 + c8];
    }

    const int jq = lane >> 3, rr = lane & 7;
    const uint32_t aAddr = sb + (uint32_t)(w * 16 + (lane & 15)) * FPITCH
                         + (lane >> 4) * 16;
    const uint32_t bBase = (uint32_t)((jq >> 1) * 8 + rr) * FPITCH
                         + (jq & 1) * 16;

    const int gid = lane >> 2, tg = lane & 3;
    const int rowA = w * 16 + gid;
    const int rowB = rowA + 8;

    float o[8][4];
    #pragma unroll
    for (int nt = 0; nt < 8; nt++)
        #pragma unroll
        for (int e = 0; e < 4; e++) o[nt][e] = 0.0f;
    float mA = -1e30f, mB = -1e30f, lA = 0.0f, lB = 0.0f;

    for (int kt = 0; kt <= qt; kt++) {
        __syncthreads();
        #pragma unroll
        for (int ii = 0; ii < 4; ii++) {
            int idx = tid + 128 * ii;
            int r = idx >> 3, c8 = (idx & 7) * 8;
            uint32_t so = (uint32_t)r * FPITCH + c8 * 2;
            *(uint4*)(smem + SKH + so) = *(const uint4*)&Kh[(kt * 64 + r) * 64 + c8];
            *(uint4*)(smem + SKL + so) = *(const uint4*)&Kl[(kt * 64 + r) * 64 + c8];
            *(uint4*)(smem + SVH + so) = *(const uint4*)&Vh[(size_t)r * Tt + kt * 64 + c8];
            *(uint4*)(smem + SVL + so) = *(const uint4*)&Vl[(size_t)r * Tt + kt * 64 + c8];
        }
        __syncthreads();

        float c[8][4];
        #pragma unroll
        for (int nt = 0; nt < 8; nt++)
            #pragma unroll
            for (int e = 0; e < 4; e++) c[nt][e] = 0.0f;

        #pragma unroll
        for (int kk = 0; kk < 4; kk++) {
            uint32_t aH[4], aL[4];
            LDSM4(aH[0], aH[1], aH[2], aH[3], aAddr + SQH + kk * 32);
            LDSM4(aL[0], aL[1], aL[2], aL[3], aAddr + SQL + kk * 32);
            #pragma unroll
            for (int pf = 0; pf < 4; pf++) {
                uint32_t bH[4], bL[4];
                uint32_t ba = sb + bBase + (uint32_t)pf * 16 * FPITCH + kk * 32;
                LDSM4(bH[0], bH[1], bH[2], bH[3], ba + SKH);
                LDSM4(bL[0], bL[1], bL[2], bL[3], ba + SKL);
                const int nt0 = pf * 2;
                mma16816(c[nt0],     aH, bH[0], bH[1]);
                mma16816(c[nt0],     aH, bL[0], bL[1]);
                mma16816(c[nt0],     aL, bH[0], bH[1]);
                mma16816(c[nt0 + 1], aH, bH[2], bH[3]);
                mma16816(c[nt0 + 1], aH, bL[2], bL[3]);
                mma16816(c[nt0 + 1], aL, bH[2], bH[3]);
            }
        }

        if (kt == qt) {
            #pragma unroll
            for (int nt = 0; nt < 8; nt++) {
                const int colb = nt * 8 + tg * 2;
                if (colb     > rowA) c[nt][0] = -1e30f;
                if (colb + 1 > rowA) c[nt][1] = -1e30f;
                if (colb     > rowB) c[nt][2] = -1e30f;
                if (colb + 1 > rowB) c[nt][3] = -1e30f;
            }
        }

        float tmA = -1e30f, tmB = -1e30f;
        #pragma unroll
        for (int nt = 0; nt < 8; nt++) {
            tmA = fmaxf(tmA, fmaxf(c[nt][0], c[nt][1]));
            tmB = fmaxf(tmB, fmaxf(c[nt][2], c[nt][3]));
        }
        tmA = fmaxf(tmA, __shfl_xor_sync(0xffffffffu, tmA, 1));
        tmA = fmaxf(tmA, __shfl_xor_sync(0xffffffffu, tmA, 2));
        tmB = fmaxf(tmB, __shfl_xor_sync(0xffffffffu, tmB, 1));
        tmB = fmaxf(tmB, __shfl_xor_sync(0xffffffffu, tmB, 2));

        const float mnA = fmaxf(mA, tmA), mnB = fmaxf(mB, tmB);
        const float alA = __expf(mA - mnA), alB = __expf(mB - mnB);
        mA = mnA; mB = mnB;

        float sA = 0.0f, sB = 0.0f;
        #pragma unroll
        for (int nt = 0; nt < 8; nt++) {
            c[nt][0] = __expf(c[nt][0] - mnA); sA += c[nt][0];
            c[nt][1] = __expf(c[nt][1] - mnA); sA += c[nt][1];
            c[nt][2] = __expf(c[nt][2] - mnB); sB += c[nt][2];
            c[nt][3] = __expf(c[nt][3] - mnB); sB += c[nt][3];
        }
        sA += __shfl_xor_sync(0xffffffffu, sA, 1);
        sA += __shfl_xor_sync(0xffffffffu, sA, 2);
        sB += __shfl_xor_sync(0xffffffffu, sB, 1);
        sB += __shfl_xor_sync(0xffffffffu, sB, 2);
        lA = lA * alA + sA;
        lB = lB * alB + sB;
        #pragma unroll
        for (int nt = 0; nt < 8; nt++) {
            o[nt][0] *= alA; o[nt][1] *= alA;
            o[nt][2] *= alB; o[nt][3] *= alB;
        }

        #pragma unroll
        for (int ks = 0; ks < 4; ks++) {
            uint32_t pH[4], pL[4];
            split2(c[2*ks][0],     c[2*ks][1],     pH[0], pL[0]);
            split2(c[2*ks][2],     c[2*ks][3],     pH[1], pL[1]);
            split2(c[2*ks + 1][0], c[2*ks + 1][1], pH[2], pL[2]);
            split2(c[2*ks + 1][2], c[2*ks + 1][3], pH[3], pL[3]);
            #pragma unroll
            for (int pfd = 0; pfd < 4; pfd++) {
                uint32_t bH[4], bL[4];
                uint32_t ba = sb + bBase + (uint32_t)pfd * 16 * FPITCH + ks * 32;
                LDSM4(bH[0], bH[1], bH[2], bH[3], ba + SVH);
                LDSM4(bL[0], bL[1], bL[2], bL[3], ba + SVL);
                const int nd = pfd * 2;
                mma16816(o[nd],     pH, bH[0], bH[1]);
                mma16816(o[nd],     pH, bL[0], bL[1]);
                mma16816(o[nd],     pL, bH[0], bH[1]);
                mma16816(o[nd + 1], pH, bH[2], bH[3]);
                mma16816(o[nd + 1], pH, bL[2], bL[3]);
                mma16816(o[nd + 1], pL, bH[2], bH[3]);
            }
        }
    }

    const int b = bh >> 4, h = bh & 15;
    const float invA = 1.0f / lA, invB = 1.0f / lB;
    const size_t ybA = ((size_t)(b * Tt + qt * 64 + rowA)) * Cc + h * HDIM;
    const size_t ybB = ((size_t)(b * Tt + qt * 64 + rowB)) * Cc + h * HDIM;
    #pragma unroll
    for (int nt = 0; nt < 8; nt++) {
        const int d = nt * 8 + tg * 2;
        uint32_t hi, lo;
        split2(o[nt][0] * invA, o[nt][1] * invA, hi, lo);
        *(uint32_t*)&g_yhi[ybA + d] = hi;
        *(uint32_t*)&g_ylo[ybA + d] = lo;
        split2(o[nt][2] * invB, o[nt][3] * invB, hi, lo);
        *(uint32_t*)&g_yhi[ybB + d] = hi;
        *(uint32_t*)&g_ylo[ybB + d] = lo;
    }
}

// ---------------------------------------------------------------------------
extern "C" void kernel_launch(void* const* d_in, const int* in_sizes, int n_in,
                              void* d_out, int out_size)
{
    (void)in_sizes; (void)n_in; (void)out_size;
    const float* x   = (const float*)d_in[0];
    const float* ipw = (const float*)d_in[1];
    const float* ipb = (const float*)d_in[2];
    const float* opw = (const float*)d_in[3];
    const float* opb = (const float*)d_in[4];
    float* out = (float*)d_out;

    cudaFuncSetAttribute(gemm_bf16x3<0>,
                         cudaFuncAttributeMaxDynamicSharedMemorySize, GEMM_SMEM);
    cudaFuncSetAttribute(gemm_bf16x3<1>,
                         cudaFuncAttributeMaxDynamicSharedMemorySize, GEMM_SMEM);
    cudaFuncSetAttribute(flash_attn_kernel,
                         cudaFuncAttributeMaxDynamicSharedMemorySize, FL_SMEM);

    // 0) hi/lo bf16 conversions of x and weights
    cvt_kernel<0><<<(Mm*Cc/4 + 255)/256, 256>>>(x,   Mm*Cc/4);
    cvt_kernel<1><<<(N1*Cc/4 + 255)/256, 256>>>(ipw, N1*Cc/4);
    cvt_kernel<2><<<(Cc*Cc/4 + 255)/256, 256>>>(opw, Cc*Cc/4);

    // 1) QKV projection + bias + FUSED RoPE -> Q,K bf16 hi/lo; V^T bf16 hi/lo
    {
        dim3 grid(N1 / 128, Mm / 128);
        gemm_bf16x3<0><<<grid, 256, GEMM_SMEM>>>(ipb, nullptr);
    }

    // 2) tensor-core causal flash attention -> g_yhi/g_ylo
    {
        dim3 grid(Tt / 64, BHt);
        flash_attn_kernel<<<grid, 128, FL_SMEM>>>();
    }

    // 3) output projection + bias
    {
        dim3 grid(Cc / 128, Mm / 128);
        gemm_bf16x3<1><<<grid, 256, GEMM_SMEM>>>(opb, out);
    }
}

// round 9
// speedup vs baseline: 1.6368x; 1.3799x over previous
#include <cuda_runtime.h>
#include <cuda_fp16.h>
#include <math.h>
#include <stdint.h>

#define Bb 8
#define Tt 1024
#define Cc 1024
#define NHEAD 16
#define HDIM 64
#define BHt (Bb*NHEAD)     // 128
#define Mm (Bb*Tt)         // 8192
#define N1 (3*Cc)          // 3072
#define KT 32              // 1024/32 k-tiles

// ------------------------- device scratch (no allocs allowed) --------------
__device__ __half g_xhi[(size_t)Mm*Cc],  g_xlo[(size_t)Mm*Cc];
__device__ __half g_w1h[(size_t)N1*Cc];                    // weights single fp16
__device__ __half g_w2h[(size_t)Cc*Cc];
__device__ __half g_yhi[(size_t)Mm*Cc],  g_ylo[(size_t)Mm*Cc];
__device__ __half g_Qhi[(size_t)BHt*Tt*HDIM], g_Qlo[(size_t)BHt*Tt*HDIM]; // post-rope, x0.125
__device__ __half g_Kh [(size_t)BHt*Tt*HDIM];              // post-rope, single fp16
__device__ __half g_Vth[(size_t)BHt*HDIM*Tt];              // [bh][d][t], single fp16

// ------------------------------ PTX helpers --------------------------------
__device__ __forceinline__ uint32_t smem_u32(const void* p) {
    uint32_t a;
    asm("{ .reg .u64 t; cvta.to.shared.u64 t, %1; cvt.u32.u64 %0, t; }"
        : "=r"(a) : "l"(p));
    return a;
}

#define CP16(dst, src) \
    asm volatile("cp.async.cg.shared.global [%0], [%1], 16;" \
                 :: "r"(dst), "l"(src) : "memory")
#define CP_COMMIT() asm volatile("cp.async.commit_group;" ::: "memory")
#define CP_WAIT1()  asm volatile("cp.async.wait_group 1;" ::: "memory")
#define CP_WAIT0()  asm volatile("cp.async.wait_group 0;" ::: "memory")

#define LDSM4(r0, r1, r2, r3, a) \
    asm volatile("ldmatrix.sync.aligned.m8n8.x4.shared.b16 {%0,%1,%2,%3}, [%4];" \
                 : "=r"(r0), "=r"(r1), "=r"(r2), "=r"(r3) : "r"(a))

__device__ __forceinline__ void mma16816(float c[4], const uint32_t a[4],
                                         uint32_t b0, uint32_t b1) {
    asm volatile("mma.sync.aligned.m16n8k16.row.col.f32.f16.f16.f32 "
                 "{%0,%1,%2,%3}, {%4,%5,%6,%7}, {%8,%9}, {%0,%1,%2,%3};"
                 : "+f"(c[0]), "+f"(c[1]), "+f"(c[2]), "+f"(c[3])
                 : "r"(a[0]), "r"(a[1]), "r"(a[2]), "r"(a[3]),
                   "r"(b0), "r"(b1));
}

// two floats -> packed fp16x2 hi + residual lo
__device__ __forceinline__ void split2h(float x, float y, uint32_t& hi, uint32_t& lo) {
    __half2 h = __floats2half2_rn(x, y);
    float2 hf = __half22float2(h);
    __half2 l = __floats2half2_rn(x - hf.x, y - hf.y);
    hi = *reinterpret_cast<uint32_t*>(&h);
    lo = *reinterpret_cast<uint32_t*>(&l);
}
__device__ __forceinline__ uint32_t pack2h(float x, float y) {
    __half2 h = __floats2half2_rn(x, y);
    return *reinterpret_cast<uint32_t*>(&h);
}

// ---------------------------------------------------------------------------
// fp32 -> fp16 conversions.  W=0: x -> hi/lo.  W=1: w1 -> single.  W=2: w2.
// ---------------------------------------------------------------------------
template<int W>
__global__ __launch_bounds__(256)
void cvt_kernel(const float* __restrict__ src, int n4)
{
    int i = blockIdx.x * blockDim.x + threadIdx.x;
    if (i >= n4) return;
    float4 v = ((const float4*)src)[i];
    if (W == 0) {
        uint32_t h01, l01, h23, l23;
        split2h(v.x, v.y, h01, l01);
        split2h(v.z, v.w, h23, l23);
        ((uint2*)g_xhi)[i] = make_uint2(h01, h23);
        ((uint2*)g_xlo)[i] = make_uint2(l01, l23);
    } else {
        uint2 o = make_uint2(pack2h(v.x, v.y), pack2h(v.z, v.w));
        if (W == 1) ((uint2*)g_w1h)[i] = o;
        else        ((uint2*)g_w2h)[i] = o;
    }
}

// ---------------------------------------------------------------------------
// fp16x2 NT GEMM via mma.sync: 128x128 block, 256 thr, 8 warps (2x4, 64x32).
// D = A_hi*B + A_lo*B (B single fp16).  Double-buffered cp.async, 80B pitch.
// MODE 0: qkv = x @ w1^T + b, fused RoPE epilogue -> Qhi/Qlo, Kh, Vt.
// MODE 1: out = y @ w2^T + b (y = hi/lo from flash).
// ---------------------------------------------------------------------------
#define T_AHI 0
#define T_ALO 10240
#define T_BH  20480
#define STAGE_BYTES 30720
#define GEMM_SMEM (2*STAGE_BYTES)

#define ROPE_LN_OVER_32 0.2878231366242557f   // ln(10000)/32

__device__ __forceinline__ void gemm_prefetch(uint32_t sdst,
    const __half* a_hi, const __half* a_lo, const __half* b_h)
{
    CP16(sdst + T_AHI,      a_hi);
    CP16(sdst + T_AHI + 16, a_hi + 8);
    CP16(sdst + T_ALO,      a_lo);
    CP16(sdst + T_ALO + 16, a_lo + 8);
    CP16(sdst + T_BH,       b_h);
    CP16(sdst + T_BH  + 16, b_h + 8);
}

// Epilogue scatter with fused RoPE. v = (col d, col d+1), d even.
__device__ __forceinline__ void scatter_qkv(int m, int n, float2 v)
{
    const int which = n >> 10, c = n & 1023;
    const int h = c >> 6, d = c & 63;
    const int b = m >> 10, t = m & 1023, bh = b * NHEAD + h;
    if (which == 2) {
        size_t i0 = ((size_t)bh * HDIM + d) * Tt + t;
        g_Vth[i0]      = __float2half(v.x);
        g_Vth[i0 + Tt] = __float2half(v.y);
        return;
    }
    // RoPE rotation for pair index i = d/2
    const float inv = expf(-(float)(d >> 1) * ROPE_LN_OVER_32);
    float sv, cv;
    sincosf((float)t * inv, &sv, &cv);
    float r1 = v.x * cv - v.y * sv;
    float r2 = v.y * cv + v.x * sv;
    const size_t base = ((size_t)bh * Tt + t) * HDIM + d;
    if (which == 0) {
        uint32_t hi, lo;
        split2h(r1 * 0.125f, r2 * 0.125f, hi, lo);   // Q pre-scaled 1/sqrt(hd)
        *(uint32_t*)&g_Qhi[base] = hi;
        *(uint32_t*)&g_Qlo[base] = lo;
    } else {
        *(uint32_t*)&g_Kh[base] = pack2h(r1, r2);
    }
}

template<int MODE>
__global__ __launch_bounds__(256)
void gemm_fp16x2(const float* __restrict__ bias, float* __restrict__ Cout)
{
    extern __shared__ char smem[];
    const uint32_t sb = smem_u32(smem);
    const int tid  = threadIdx.x;
    const int lane = tid & 31, wid = tid >> 5;
    const int wm = wid >> 2, wn = wid & 3;         // 2 x 4 warp grid, 64x32 tiles
    const int m0 = blockIdx.y * 128, n0 = blockIdx.x * 128;

    const __half* Ahi = (MODE == 0) ? g_xhi : g_yhi;
    const __half* Alo = (MODE == 0) ? g_xlo : g_ylo;
    const __half* Bh  = (MODE == 0) ? g_w1h : g_w2h;

    const int lr = tid >> 1;
    const int lh = tid & 1;
    const size_t gA = (size_t)(m0 + lr) * Cc + lh * 16;
    const size_t gB = (size_t)(n0 + lr) * Cc + lh * 16;
    const uint32_t sOff = (uint32_t)lr * 80 + lh * 32;

    const int jq = lane >> 3, rr = lane & 7;
    const int aRow  = wm * 64 + (jq & 1) * 8 + rr;
    const int aColB = (jq >> 1) * 16;
    const int bRow  = wn * 32 + (jq >> 1) * 8 + rr;
    const int bColB = (jq & 1) * 16;

    float acc[4][4][4];
    #pragma unroll
    for (int i = 0; i < 4; i++)
        #pragma unroll
        for (int j = 0; j < 4; j++)
            #pragma unroll
            for (int e = 0; e < 4; e++) acc[i][j][e] = 0.0f;

    gemm_prefetch(sb + sOff, Ahi + gA, Alo + gA, Bh + gB);
    CP_COMMIT();

    for (int kt = 0; kt < KT; kt++) {
        const int cur = kt & 1;
        if (kt + 1 < KT) {
            const size_t ko = (size_t)(kt + 1) * 32;
            gemm_prefetch(sb + ((kt + 1) & 1) * STAGE_BYTES + sOff,
                          Ahi + gA + ko, Alo + gA + ko, Bh + gB + ko);
            CP_COMMIT();
            CP_WAIT1();
        } else {
            CP_WAIT0();
        }
        __syncthreads();

        const uint32_t base = sb + cur * STAGE_BYTES;
        #pragma unroll
        for (int kk = 0; kk < 2; kk++) {
            const uint32_t kB = kk * 32;
            uint32_t ah[4][4], al[4][4], bh[2][4];
            #pragma unroll
            for (int mf = 0; mf < 4; mf++) {
                uint32_t addr = base + (uint32_t)(aRow + mf * 16) * 80 + aColB + kB;
                LDSM4(ah[mf][0], ah[mf][1], ah[mf][2], ah[mf][3], addr + T_AHI);
                LDSM4(al[mf][0], al[mf][1], al[mf][2], al[mf][3], addr + T_ALO);
            }
            #pragma unroll
            for (int pf = 0; pf < 2; pf++) {
                uint32_t addr = base + (uint32_t)(bRow + pf * 16) * 80 + bColB + kB;
                LDSM4(bh[pf][0], bh[pf][1], bh[pf][2], bh[pf][3], addr + T_BH);
            }
            #pragma unroll
            for (int mf = 0; mf < 4; mf++) {
                #pragma unroll
                for (int nt = 0; nt < 4; nt++) {
                    const int pf = nt >> 1, ix = (nt & 1) * 2;
                    mma16816(acc[mf][nt], ah[mf], bh[pf][ix], bh[pf][ix + 1]);
                    mma16816(acc[mf][nt], al[mf], bh[pf][ix], bh[pf][ix + 1]);
                }
            }
        }
        __syncthreads();
    }

    const int gid = lane >> 2, tg = lane & 3;
    #pragma unroll
    for (int mf = 0; mf < 4; mf++) {
        #pragma unroll
        for (int nt = 0; nt < 4; nt++) {
            const int n = n0 + wn * 32 + nt * 8 + tg * 2;
            const float2 bv = *(const float2*)&bias[n];
            const int mA = m0 + wm * 64 + mf * 16 + gid;
            float2 v01 = make_float2(acc[mf][nt][0] + bv.x, acc[mf][nt][1] + bv.y);
            float2 v23 = make_float2(acc[mf][nt][2] + bv.x, acc[mf][nt][3] + bv.y);
            if (MODE == 0) {
                scatter_qkv(mA,     n, v01);
                scatter_qkv(mA + 8, n, v23);
            } else {
                *(float2*)&Cout[(size_t)mA * Cc + n]       = v01;
                *(float2*)&Cout[(size_t)(mA + 8) * Cc + n] = v23;
            }
        }
    }
}

// ---------------------------------------------------------------------------
// Tensor-core flash attention (fp16x2), causal. Block = (qt, bh), 128 thr.
// S = (Qhi + Qlo) K^T,  o = (Phi + Plo) V.  K, V single fp16.
// Smem: Qhi Qlo Kh Vh, 64x72 fp16 tiles (pitch 144B).
// ---------------------------------------------------------------------------
#define FPITCH 144
#define SQH 0
#define SQL 9216
#define SKH 18432
#define SVH 27648
#define FL_SMEM 36864

__global__ __launch_bounds__(128)
void flash_attn_kernel()
{
    extern __shared__ char smem[];
    const uint32_t sb = smem_u32(smem);
    const int tid  = threadIdx.x;
    const int lane = tid & 31, w = tid >> 5;
    const int qt = blockIdx.x;     // 0..15
    const int bh = blockIdx.y;     // 0..127

    const __half* Qh = g_Qhi + ((size_t)bh * Tt + qt * 64) * HDIM;
    const __half* Ql = g_Qlo + ((size_t)bh * Tt + qt * 64) * HDIM;
    const __half* Kh = g_Kh  + (size_t)bh * Tt * HDIM;
    const __half* Vh = g_Vth + (size_t)bh * HDIM * Tt;

    #pragma unroll
    for (int ii = 0; ii < 4; ii++) {
        int idx = tid + 128 * ii;
        int r = idx >> 3, c8 = (idx & 7) * 8;
        uint32_t so = (uint32_t)r * FPITCH + c8 * 2;
        *(uint4*)(smem + SQH + so) = *(const uint4*)&Qh[r * 64 + c8];
        *(uint4*)(smem + SQL + so) = *(const uint4*)&Ql[r * 64 + c8];
    }

    const int jq = lane >> 3, rr = lane & 7;
    const uint32_t aAddr = sb + (uint32_t)(w * 16 + (lane & 15)) * FPITCH
                         + (lane >> 4) * 16;
    const uint32_t bBase = (uint32_t)((jq >> 1) * 8 + rr) * FPITCH
                         + (jq & 1) * 16;

    const int gid = lane >> 2, tg = lane & 3;
    const int rowA = w * 16 + gid;
    const int rowB = rowA + 8;

    float o[8][4];
    #pragma unroll
    for (int nt = 0; nt < 8; nt++)
        #pragma unroll
        for (int e = 0; e < 4; e++) o[nt][e] = 0.0f;
    float mA = -1e30f, mB = -1e30f, lA = 0.0f, lB = 0.0f;

    for (int kt = 0; kt <= qt; kt++) {
        __syncthreads();
        #pragma unroll
        for (int ii = 0; ii < 4; ii++) {
            int idx = tid + 128 * ii;
            int r = idx >> 3, c8 = (idx & 7) * 8;
            uint32_t so = (uint32_t)r * FPITCH + c8 * 2;
            *(uint4*)(smem + SKH + so) = *(const uint4*)&Kh[(kt * 64 + r) * 64 + c8];
            *(uint4*)(smem + SVH + so) = *(const uint4*)&Vh[(size_t)r * Tt + kt * 64 + c8];
        }
        __syncthreads();

        float c[8][4];
        #pragma unroll
        for (int nt = 0; nt < 8; nt++)
            #pragma unroll
            for (int e = 0; e < 4; e++) c[nt][e] = 0.0f;

        #pragma unroll
        for (int kk = 0; kk < 4; kk++) {
            uint32_t aH[4], aL[4];
            LDSM4(aH[0], aH[1], aH[2], aH[3], aAddr + SQH + kk * 32);
            LDSM4(aL[0], aL[1], aL[2], aL[3], aAddr + SQL + kk * 32);
            #pragma unroll
            for (int pf = 0; pf < 4; pf++) {
                uint32_t bH[4];
                uint32_t ba = sb + bBase + (uint32_t)pf * 16 * FPITCH + kk * 32;
                LDSM4(bH[0], bH[1], bH[2], bH[3], ba + SKH);
                const int nt0 = pf * 2;
                mma16816(c[nt0],     aH, bH[0], bH[1]);
                mma16816(c[nt0],     aL, bH[0], bH[1]);
                mma16816(c[nt0 + 1], aH, bH[2], bH[3]);
                mma16816(c[nt0 + 1], aL, bH[2], bH[3]);
            }
        }

        if (kt == qt) {
            #pragma unroll
            for (int nt = 0; nt < 8; nt++) {
                const int colb = nt * 8 + tg * 2;
                if (colb     > rowA) c[nt][0] = -1e30f;
                if (colb + 1 > rowA) c[nt][1] = -1e30f;
                if (colb     > rowB) c[nt][2] = -1e30f;
                if (colb + 1 > rowB) c[nt][3] = -1e30f;
            }
        }

        float tmA = -1e30f, tmB = -1e30f;
        #pragma unroll
        for (int nt = 0; nt < 8; nt++) {
            tmA = fmaxf(tmA, fmaxf(c[nt][0], c[nt][1]));
            tmB = fmaxf(tmB, fmaxf(c[nt][2], c[nt][3]));
        }
        tmA = fmaxf(tmA, __shfl_xor_sync(0xffffffffu, tmA, 1));
        tmA = fmaxf(tmA, __shfl_xor_sync(0xffffffffu, tmA, 2));
        tmB = fmaxf(tmB, __shfl_xor_sync(0xffffffffu, tmB, 1));
        tmB = fmaxf(tmB, __shfl_xor_sync(0xffffffffu, tmB, 2));

        const float mnA = fmaxf(mA, tmA), mnB = fmaxf(mB, tmB);
        const float alA = __expf(mA - mnA), alB = __expf(mB - mnB);
        mA = mnA; mB = mnB;

        float sA = 0.0f, sB = 0.0f;
        #pragma unroll
        for (int nt = 0; nt < 8; nt++) {
            c[nt][0] = __expf(c[nt][0] - mnA); sA += c[nt][0];
            c[nt][1] = __expf(c[nt][1] - mnA); sA += c[nt][1];
            c[nt][2] = __expf(c[nt][2] - mnB); sB += c[nt][2];
            c[nt][3] = __expf(c[nt][3] - mnB); sB += c[nt][3];
        }
        sA += __shfl_xor_sync(0xffffffffu, sA, 1);
        sA += __shfl_xor_sync(0xffffffffu, sA, 2);
        sB += __shfl_xor_sync(0xffffffffu, sB, 1);
        sB += __shfl_xor_sync(0xffffffffu, sB, 2);
        lA = lA * alA + sA;
        lB = lB * alB + sB;
        #pragma unroll
        for (int nt = 0; nt < 8; nt++) {
            o[nt][0] *= alA; o[nt][1] *= alA;
            o[nt][2] *= alB; o[nt][3] *= alB;
        }

        #pragma unroll
        for (int ks = 0; ks < 4; ks++) {
            uint32_t pH[4], pL[4];
            split2h(c[2*ks][0],     c[2*ks][1],     pH[0], pL[0]);
            split2h(c[2*ks][2],     c[2*ks][3],     pH[1], pL[1]);
            split2h(c[2*ks + 1][0], c[2*ks + 1][1], pH[2], pL[2]);
            split2h(c[2*ks + 1][2], c[2*ks + 1][3], pH[3], pL[3]);
            #pragma unroll
            for (int pfd = 0; pfd < 4; pfd++) {
                uint32_t bH[4];
                uint32_t ba = sb + bBase + (uint32_t)pfd * 16 * FPITCH + ks * 32;
                LDSM4(bH[0], bH[1], bH[2], bH[3], ba + SVH);
                const int nd = pfd * 2;
                mma16816(o[nd],     pH, bH[0], bH[1]);
                mma16816(o[nd],     pL, bH[0], bH[1]);
                mma16816(o[nd + 1], pH, bH[2], bH[3]);
                mma16816(o[nd + 1], pL, bH[2], bH[3]);
            }
        }
    }

    const int b = bh >> 4, h = bh & 15;
    const float invA = 1.0f / lA, invB = 1.0f / lB;
    const size_t ybA = ((size_t)(b * Tt + qt * 64 + rowA)) * Cc + h * HDIM;
    const size_t ybB = ((size_t)(b * Tt + qt * 64 + rowB)) * Cc + h * HDIM;
    #pragma unroll
    for (int nt = 0; nt < 8; nt++) {
        const int d = nt * 8 + tg * 2;
        uint32_t hi, lo;
        split2h(o[nt][0] * invA, o[nt][1] * invA, hi, lo);
        *(uint32_t*)&g_yhi[ybA + d] = hi;
        *(uint32_t*)&g_ylo[ybA + d] = lo;
        split2h(o[nt][2] * invB, o[nt][3] * invB, hi, lo);
        *(uint32_t*)&g_yhi[ybB + d] = hi;
        *(uint32_t*)&g_ylo[ybB + d] = lo;
    }
}

// ---------------------------------------------------------------------------
extern "C" void kernel_launch(void* const* d_in, const int* in_sizes, int n_in,
                              void* d_out, int out_size)
{
    (void)in_sizes; (void)n_in; (void)out_size;
    const float* x   = (const float*)d_in[0];
    const float* ipw = (const float*)d_in[1];
    const float* ipb = (const float*)d_in[2];
    const float* opw = (const float*)d_in[3];
    const float* opb = (const float*)d_in[4];
    float* out = (float*)d_out;

    cudaFuncSetAttribute(gemm_fp16x2<0>,
                         cudaFuncAttributeMaxDynamicSharedMemorySize, GEMM_SMEM);
    cudaFuncSetAttribute(gemm_fp16x2<1>,
                         cudaFuncAttributeMaxDynamicSharedMemorySize, GEMM_SMEM);
    cudaFuncSetAttribute(flash_attn_kernel,
                         cudaFuncAttributeMaxDynamicSharedMemorySize, FL_SMEM);

    // 0) fp16 conversions: x -> hi/lo, weights -> single fp16
    cvt_kernel<0><<<(Mm*Cc/4 + 255)/256, 256>>>(x,   Mm*Cc/4);
    cvt_kernel<1><<<(N1*Cc/4 + 255)/256, 256>>>(ipw, N1*Cc/4);
    cvt_kernel<2><<<(Cc*Cc/4 + 255)/256, 256>>>(opw, Cc*Cc/4);

    // 1) QKV projection + bias + fused RoPE -> Qhi/Qlo, Kh, Vt (fp16)
    {
        dim3 grid(N1 / 128, Mm / 128);
        gemm_fp16x2<0><<<grid, 256, GEMM_SMEM>>>(ipb, nullptr);
    }

    // 2) tensor-core causal flash attention -> g_yhi/g_ylo
    {
        dim3 grid(Tt / 64, BHt);
        flash_attn_kernel<<<grid, 128, FL_SMEM>>>();
    }

    // 3) output projection + bias (256 threads!)
    {
        dim3 grid(Cc / 128, Mm / 128);
        gemm_fp16x2<1><<<grid, 256, GEMM_SMEM>>>(opb, out);
    }
}